// round 16
// baseline (speedup 1.0000x reference)
#include <cuda_runtime.h>

#define NCTA   128
#define NTHR   512
#define GSZ    256          // threads per K-group
#define D      1024
#define KHALF  512
#define BATCH  64
#define KT     64
#define NT_G   8            // tiles per K-group
#define STR    68
#define SEQL   192
#define DECLEN 216
#define LABELN 48
#define PREDN  168

typedef unsigned long long ull;

// ---------------- persistent device state -----------------------------------
__device__ float    g_h0[2][BATCH * D];
__device__ float    g_h1[2][BATCH * D];
__device__ float    g_pred[BATCH * 8];
__device__ unsigned g_arrive;
__device__ unsigned g_release;

// ---------------- smem layout (floats) ---------------------------------------
// per K-group block (23936 floats):
//   SW: 2*48*STR = 6528 | SH: 2*64*STR = 8704 | SX: 2*64*STR = 8704
// then: SXS 768 | SRED 128 | SWSM 528 | SPART 2048
// total = 2*23936 + 3472 = 51344 floats = 205376 B
#define GBLK 23936
#define SMEM_FLOATS 51344
extern __shared__ float smem[];
#define SW(g,buf)  (smem + (g) * GBLK + (buf) * (48 * STR))
#define SH(g,buf)  (smem + (g) * GBLK + 6528 + (buf) * (64 * STR))
#define SX(g,buf)  (smem + (g) * GBLK + 15232 + (buf) * (64 * STR))
#define SXS        (smem + 2 * GBLK)
#define SRED       (smem + 2 * GBLK + 768)
#define SWSM       (smem + 2 * GBLK + 896)
#define SPART      (smem + 2 * GBLK + 1424)

// ---------------- helpers ----------------------------------------------------
__device__ __forceinline__ void ffma2(ull& acc, ull a, ull b) {
    asm("fma.rn.f32x2 %0, %1, %2, %0;" : "+l"(acc) : "l"(a), "l"(b));
}
__device__ __forceinline__ float hadd2(ull v) {
    float lo, hi;
    asm("mov.b64 {%0,%1}, %2;" : "=f"(lo), "=f"(hi) : "l"(v));
    return lo + hi;
}
__device__ __forceinline__ float sigmoidf_(float x) {
    return 1.0f / (1.0f + __expf(-x));
}
__device__ __forceinline__ void cpasync16(float* sdst, const float* gsrc) {
    unsigned s = (unsigned)__cvta_generic_to_shared(sdst);
    asm volatile("cp.async.cg.shared.global [%0], [%1], 16;" :: "r"(s), "l"(gsrc));
}
#define CP_COMMIT()  asm volatile("cp.async.commit_group;" ::: "memory")
#define CP_WAIT0()   asm volatile("cp.async.wait_group 0;" ::: "memory")

// grid-wide barrier (128 CTAs, 1/SM, all co-resident)
__device__ __forceinline__ void grid_sync(unsigned barNo) {
    __syncthreads();
    if (threadIdx.x == 0) {
        __threadfence();
        unsigned a = atomicAdd(&g_arrive, 1u);
        if (a + 1u == barNo * (unsigned)NCTA) {
            __threadfence();
            atomicAdd(&g_release, 1u);
        } else {
            unsigned r;
            do {
                asm volatile("ld.acquire.gpu.u32 %0, [%1];" : "=r"(r) : "l"(&g_release));
            } while (r < barNo);
        }
    }
    __syncthreads();
}

// ---------------- tile staging (cp.async), one K-group -----------------------
template <bool HASX>
__device__ __forceinline__ void stage_tile(
    int g, int buf, int ktg, int t8, int col0,
    const float* __restrict__ Wih, const float* __restrict__ Whh,
    const float* __restrict__ hprev, const float* __restrict__ xfull)
{
    float* sh = SH(g, buf);
    float* sx = SX(g, buf);
    float* sw = SW(g, buf);
#pragma unroll
    for (int i = t8; i < BATCH * 16; i += GSZ) {
        int b = i >> 4, sg = i & 15;
        cpasync16(sh + b * STR + sg * 4, hprev + b * D + ktg + sg * 4);
    }
    if (HASX) {
#pragma unroll
        for (int i = t8; i < BATCH * 16; i += GSZ) {
            int b = i >> 4, sg = i & 15;
            cpasync16(sx + b * STR + sg * 4, xfull + b * D + ktg + sg * 4);
        }
    }
    const int NR = HASX ? 48 : 24;
    for (int i = t8; i < NR * 16; i += GSZ) {
        int r = i >> 4, sg = i & 15;
        const float* src = (HASX && r < 24) ? Wih : Whh;
        int rr = (HASX && r >= 24) ? (r - 24) : r;
        int gg = rr >> 3, c = rr & 7;
        cpasync16(sw + r * STR + sg * 4,
                  src + (size_t)(gg * D + col0 + c) * D + ktg + sg * 4);
    }
}

// ---------------- one GRU layer step (this CTA's 8 columns) ------------------
// tid: g = tid>>8 (K-group); t8 = tid&255: bg=t8&7, cl=(t8>>3)&7, jh=t8>>6
// thread pair set: (col0+cl, b0=bg+16*jh) and (col0+cl, b1=b0+8); K-range by g.
template <bool HASX>
__device__ __forceinline__ void gru_layer(
    const float* __restrict__ Wih, const float* __restrict__ Whh,
    const float* __restrict__ bih, const float* __restrict__ bhh,
    const float* __restrict__ xfull,
    const float* __restrict__ hprev, float* __restrict__ hcur,
    const float* wsm_s, int col0, int tid)
{
    const int g  = tid >> 8;
    const int t8 = tid & 255;
    const int bg = t8 & 7;
    const int cl = (t8 >> 3) & 7;
    const int jh = t8 >> 6;
    const int b0 = bg + 16 * jh;
    const int b1 = b0 + 8;
    const int col = col0 + cl;
    const int hb  = HASX ? 24 : 0;

    ull aR0 = 0, aZ0 = 0, aN0 = 0, aH0 = 0;
    ull aR1 = 0, aZ1 = 0, aN1 = 0, aH1 = 0;

    // prefetch h_prev for the state update (needed only in the epilogue;
    // issue now so the L2 latency is fully hidden behind the tile loop)
    float hp0 = 0.0f, hp1 = 0.0f;
    if (g == 0) {
        hp0 = __ldcg(hprev + b0 * D + col);
        hp1 = __ldcg(hprev + b1 * D + col);
    }

    stage_tile<HASX>(g, 0, g * KHALF, t8, col0, Wih, Whh, hprev, xfull);
    CP_COMMIT();

    for (int tile = 0; tile < NT_G; tile++) {
        CP_WAIT0();
        __syncthreads();
        if (tile + 1 < NT_G) {
            stage_tile<HASX>(g, (tile + 1) & 1, g * KHALF + (tile + 1) * KT,
                             t8, col0, Wih, Whh, hprev, xfull);
            CP_COMMIT();
        }
        const float* sw = SW(g, tile & 1);
        const float* sh = SH(g, tile & 1);
        const float* sx = SX(g, tile & 1);
#pragma unroll 4
        for (int q = 0; q < KT / 4; q++) {
            const int o = 4 * q;
            ulonglong2 wHR = *(const ulonglong2*)(sw + (hb + cl) * STR + o);
            ulonglong2 wHZ = *(const ulonglong2*)(sw + (hb + 8 + cl) * STR + o);
            ulonglong2 wHN = *(const ulonglong2*)(sw + (hb + 16 + cl) * STR + o);
            ulonglong2 h0v = *(const ulonglong2*)(sh + b0 * STR + o);
            ulonglong2 h1v = *(const ulonglong2*)(sh + b1 * STR + o);
            ffma2(aR0, wHR.x, h0v.x); ffma2(aR0, wHR.y, h0v.y);
            ffma2(aZ0, wHZ.x, h0v.x); ffma2(aZ0, wHZ.y, h0v.y);
            ffma2(aH0, wHN.x, h0v.x); ffma2(aH0, wHN.y, h0v.y);
            ffma2(aR1, wHR.x, h1v.x); ffma2(aR1, wHR.y, h1v.y);
            ffma2(aZ1, wHZ.x, h1v.x); ffma2(aZ1, wHZ.y, h1v.y);
            ffma2(aH1, wHN.x, h1v.x); ffma2(aH1, wHN.y, h1v.y);
            if (HASX) {
                ulonglong2 wIR = *(const ulonglong2*)(sw + cl * STR + o);
                ulonglong2 wIZ = *(const ulonglong2*)(sw + (8 + cl) * STR + o);
                ulonglong2 wIN = *(const ulonglong2*)(sw + (16 + cl) * STR + o);
                ulonglong2 x0v = *(const ulonglong2*)(sx + b0 * STR + o);
                ulonglong2 x1v = *(const ulonglong2*)(sx + b1 * STR + o);
                ffma2(aR0, wIR.x, x0v.x); ffma2(aR0, wIR.y, x0v.y);
                ffma2(aZ0, wIZ.x, x0v.x); ffma2(aZ0, wIZ.y, x0v.y);
                ffma2(aN0, wIN.x, x0v.x); ffma2(aN0, wIN.y, x0v.y);
                ffma2(aR1, wIR.x, x1v.x); ffma2(aR1, wIR.y, x1v.y);
                ffma2(aZ1, wIZ.x, x1v.x); ffma2(aZ1, wIZ.y, x1v.y);
                ffma2(aN1, wIN.x, x1v.x); ffma2(aN1, wIN.y, x1v.y);
            }
        }
    }

    // ---- cross-K-group reduction: group 1 publishes partials ----
    if (g == 1) {
        int pid0 = cl * 64 + b0, pid1 = cl * 64 + b1;
        *(float4*)(SPART + pid0 * 4) =
            make_float4(hadd2(aR0), hadd2(aZ0), hadd2(aN0), hadd2(aH0));
        *(float4*)(SPART + pid1 * 4) =
            make_float4(hadd2(aR1), hadd2(aZ1), hadd2(aN1), hadd2(aH1));
    }
    __syncthreads();

    // ---- epilogue (group 0 only) ----
    if (g == 0) {
        float br  = __ldg(bih + col)         + __ldg(bhh + col);
        float bz  = __ldg(bih + D + col)     + __ldg(bhh + D + col);
        float bni = __ldg(bih + 2 * D + col);
        float bnh = __ldg(bhh + 2 * D + col);

#pragma unroll
        for (int i = 0; i < 2; i++) {
            int b = i ? b1 : b0;
            float4 pp = *(const float4*)(SPART + (cl * 64 + b) * 4);
            float r   = hadd2(i ? aR1 : aR0) + pp.x + br;
            float z   = hadd2(i ? aZ1 : aZ0) + pp.y + bz;
            float inn = hadd2(i ? aN1 : aN0) + pp.z + bni;
            float hn  = hadd2(i ? aH1 : aH0) + pp.w + bnh;
            if (!HASX) {
                const float* xs = &SXS[b * 12];
#pragma unroll
                for (int k = 0; k < 11; k++) {
                    float xv = xs[k];
                    r   += wsm_s[cl * 11 + k] * xv;
                    z   += wsm_s[88 + cl * 11 + k] * xv;
                    inn += wsm_s[176 + cl * 11 + k] * xv;
                }
            }
            r = sigmoidf_(r);
            z = sigmoidf_(z);
            float n  = tanhf(inn + r * hn);
            float hp = i ? hp1 : hp0;
            hcur[b * D + col] = (1.0f - z) * n + z * hp;
        }
    }
}

// ---------------- init ------------------------------------------------------
__global__ void gru_init_kernel() {
    int i = blockIdx.x * blockDim.x + threadIdx.x;
    int n = 2 * BATCH * D;
    float* a = &g_h0[0][0];
    float* b = &g_h1[0][0];
    if (i < n) { a[i] = 0.0f; b[i] = 0.0f; }
    if (i < BATCH * 8) g_pred[i] = 0.0f;
    if (i == 0) { g_arrive = 0u; g_release = 0u; }
}

// ---------------- main persistent kernel ------------------------------------
__global__ void __launch_bounds__(NTHR, 1) gru_persistent_kernel(
    const float* __restrict__ xe,  const float* __restrict__ xme,
    const float* __restrict__ xd,  const float* __restrict__ xmd,
    const float* __restrict__ eWih0, const float* __restrict__ eWhh0,
    const float* __restrict__ ebih0, const float* __restrict__ ebhh0,
    const float* __restrict__ eWih1, const float* __restrict__ eWhh1,
    const float* __restrict__ ebih1, const float* __restrict__ ebhh1,
    const float* __restrict__ dWih0, const float* __restrict__ dWhh0,
    const float* __restrict__ dbih0, const float* __restrict__ dbhh0,
    const float* __restrict__ dWih1, const float* __restrict__ dWhh1,
    const float* __restrict__ dbih1, const float* __restrict__ dbhh1,
    const float* __restrict__ outW,  const float* __restrict__ outb,
    float* __restrict__ out)
{
    const int tid  = threadIdx.x;
    const int col0 = blockIdx.x * 8;
    unsigned barNo = 0;
    int p = 0;

    // preload small-x weights (l0 enc + l0 dec) into smem once
    for (int i = tid; i < 264; i += NTHR) {
        int g = i / 88, r2 = i - g * 88;
        int c = r2 / 11, k = r2 - c * 11;
        SWSM[i]       = __ldg(eWih0 + (size_t)(g * D + col0 + c) * 11 + k);
        SWSM[264 + i] = __ldg(dWih0 + (size_t)(g * D + col0 + c) * 11 + k);
    }
    __syncthreads();

    // ================= encoder =================
    for (int t = 0; t < SEQL; t++) {
        for (int i = tid; i < BATCH * 11; i += NTHR) {
            int b = i / 11, k = i - b * 11;
            float v = (k < 7) ? __ldg(xe + (size_t)(b * SEQL + t) * 7 + k)
                              : __ldg(xme + (size_t)(b * SEQL + t) * 4 + (k - 7));
            SXS[b * 12 + k] = v;
        }
        __syncthreads();
        gru_layer<false>(eWih0, eWhh0, ebih0, ebhh0, nullptr,
                         g_h0[p], g_h0[1 - p], SWSM, col0, tid);
        barNo++; grid_sync(barNo);
        gru_layer<true>(eWih1, eWhh1, ebih1, ebhh1,
                        g_h0[1 - p], g_h1[p], g_h1[1 - p], nullptr, col0, tid);
        barNo++; grid_sync(barNo);
        p ^= 1;
    }

    // ================= decoder =================
    for (int t = 0; t < DECLEN; t++) {
        for (int i = tid; i < BATCH * 11; i += NTHR) {
            int b = i / 11, k = i - b * 11;
            float v;
            if (k >= 7)          v = __ldg(xmd + (size_t)(b * DECLEN + t) * 4 + (k - 7));
            else if (t < LABELN) v = __ldg(xd + (size_t)(b * DECLEN + t) * 7 + k);
            else                 v = __ldcg(g_pred + b * 8 + k);
            SXS[b * 12 + k] = v;
        }
        __syncthreads();
        gru_layer<false>(dWih0, dWhh0, dbih0, dbhh0, nullptr,
                         g_h0[p], g_h0[1 - p], SWSM + 264, col0, tid);
        barNo++; grid_sync(barNo);
        gru_layer<true>(dWih1, dWhh1, dbih1, dbhh1,
                        g_h0[1 - p], g_h1[p], g_h1[1 - p], nullptr, col0, tid);
        barNo++; grid_sync(barNo);

        // output projection: CTA b (< 64) computes pred[b][0..6]
        if (blockIdx.x < BATCH) {
            int b = blockIdx.x;
            const float* h1c = g_h1[1 - p];
            float acc[7] = {0, 0, 0, 0, 0, 0, 0};
#pragma unroll
            for (int kb = 0; kb < 2; kb++) {
                int k = kb * NTHR + tid;
                float hv = __ldcg(h1c + b * D + k);
#pragma unroll
                for (int j = 0; j < 7; j++)
                    acc[j] += __ldg(outW + j * D + k) * hv;
            }
#pragma unroll
            for (int j = 0; j < 7; j++)
                for (int off = 16; off; off >>= 1)
                    acc[j] += __shfl_down_sync(0xffffffffu, acc[j], off);
            int lane = tid & 31, w = tid >> 5;
            if (lane == 0) {
#pragma unroll
                for (int j = 0; j < 7; j++) SRED[w * 7 + j] = acc[j];
            }
            __syncthreads();
            if (tid < 7) {
                float s = __ldg(outb + tid);
#pragma unroll
                for (int w2 = 0; w2 < 16; w2++) s += SRED[w2 * 7 + tid];
                g_pred[b * 8 + tid] = s;
                if (t >= LABELN)
                    out[(size_t)b * (PREDN * 7) + (t - LABELN) * 7 + tid] = s;
            }
        }
        barNo++; grid_sync(barNo);
        p ^= 1;
    }
}

// ---------------- launch -----------------------------------------------------
extern "C" void kernel_launch(void* const* d_in, const int* in_sizes, int n_in,
                              void* d_out, int out_size) {
    (void)in_sizes; (void)n_in; (void)out_size;
    const float* xe    = (const float*)d_in[0];
    const float* xme   = (const float*)d_in[1];
    const float* xd    = (const float*)d_in[2];
    const float* xmd   = (const float*)d_in[3];
    const float* eWih0 = (const float*)d_in[4];
    const float* eWhh0 = (const float*)d_in[5];
    const float* ebih0 = (const float*)d_in[6];
    const float* ebhh0 = (const float*)d_in[7];
    const float* eWih1 = (const float*)d_in[8];
    const float* eWhh1 = (const float*)d_in[9];
    const float* ebih1 = (const float*)d_in[10];
    const float* ebhh1 = (const float*)d_in[11];
    const float* dWih0 = (const float*)d_in[12];
    const float* dWhh0 = (const float*)d_in[13];
    const float* dbih0 = (const float*)d_in[14];
    const float* dbhh0 = (const float*)d_in[15];
    const float* dWih1 = (const float*)d_in[16];
    const float* dWhh1 = (const float*)d_in[17];
    const float* dbih1 = (const float*)d_in[18];
    const float* dbhh1 = (const float*)d_in[19];
    const float* outW  = (const float*)d_in[20];
    const float* outb  = (const float*)d_in[21];

    static int attr_set = 0;
    if (!attr_set) {
        cudaFuncSetAttribute(gru_persistent_kernel,
                             cudaFuncAttributeMaxDynamicSharedMemorySize,
                             SMEM_FLOATS * (int)sizeof(float));
        attr_set = 1;
    }

    gru_init_kernel<<<(2 * BATCH * D + 255) / 256, 256>>>();
    gru_persistent_kernel<<<NCTA, NTHR, SMEM_FLOATS * sizeof(float)>>>(
        xe, xme, xd, xmd,
        eWih0, eWhh0, ebih0, ebhh0, eWih1, eWhh1, ebih1, ebhh1,
        dWih0, dWhh0, dbih0, dbhh0, dWih1, dWhh1, dbih1, dbhh1,
        outW, outb, (float*)d_out);
}

// round 17
// speedup vs baseline: 1.2595x; 1.2595x over previous
#include <cuda_runtime.h>

#define NCTA   128
#define NTHR   512
#define GSZ    256
#define D      1024
#define BATCH  64
#define KT     32
#define NT_G   16
#define STR    36
#define SEQL   192
#define DECLEN 216
#define LABELN 48
#define PREDN  168

typedef unsigned long long ull;

// ---------------- persistent device state -----------------------------------
__device__ float    g_h0[2][BATCH * D];
__device__ float    g_h1[2][BATCH * D];
__device__ float    g_pred[BATCH * 8];
__device__ unsigned g_arrive;
__device__ unsigned g_release;

// ---------------- smem layout (floats) ---------------------------------------
// per K-group (GBLK=14400): SW 2*72*36=5184 | SH0 2*64*36=4608 | SH1 4608
// then SXS 768 | SRED 128 | SWSM 528 | SPART 4096  → 34320 floats = 137280 B
#define GBLK 14400
#define SMEM_FLOATS 34320
extern __shared__ float smem[];
#define SWp(g,buf)  (smem + (g) * GBLK + (buf) * 2592)
#define SH0p(g,buf) (smem + (g) * GBLK + 5184 + (buf) * 2304)
#define SH1p(g,buf) (smem + (g) * GBLK + 9792 + (buf) * 2304)
#define SXS         (smem + 28800)
#define SRED        (smem + 29568)
#define SWSM        (smem + 29696)
#define SPART       (smem + 30224)

// ---------------- helpers ----------------------------------------------------
__device__ __forceinline__ void ffma2(ull& acc, ull a, ull b) {
    asm("fma.rn.f32x2 %0, %1, %2, %0;" : "+l"(acc) : "l"(a), "l"(b));
}
__device__ __forceinline__ float hadd2(ull v) {
    float lo, hi;
    asm("mov.b64 {%0,%1}, %2;" : "=f"(lo), "=f"(hi) : "l"(v));
    return lo + hi;
}
__device__ __forceinline__ float sigmoidf_(float x) {
    return 1.0f / (1.0f + __expf(-x));
}
__device__ __forceinline__ void cpasync16(float* sdst, const float* gsrc) {
    unsigned s = (unsigned)__cvta_generic_to_shared(sdst);
    asm volatile("cp.async.cg.shared.global [%0], [%1], 16;" :: "r"(s), "l"(gsrc));
}
#define CP_COMMIT()  asm volatile("cp.async.commit_group;" ::: "memory")
#define CP_WAIT0()   asm volatile("cp.async.wait_group 0;" ::: "memory")

__device__ __forceinline__ void grid_sync(unsigned barNo) {
    __syncthreads();
    if (threadIdx.x == 0) {
        __threadfence();
        unsigned a = atomicAdd(&g_arrive, 1u);
        if (a + 1u == barNo * (unsigned)NCTA) {
            __threadfence();
            atomicAdd(&g_release, 1u);
        } else {
            unsigned r;
            do {
                asm volatile("ld.acquire.gpu.u32 %0, [%1];" : "=r"(r) : "l"(&g_release));
            } while (r < barNo);
        }
    }
    __syncthreads();
}

// ---------------- accumulators -----------------------------------------------
struct Acc {
    ull aR0, aZ0, aH0, aR1, aZ1, aH1;          // l0: W_hh0 · h0   (2 batches)
    ull R0, Z0, IN0, HN0, R1, Z1, IN1, HN1;    // l1: r/z fused ih+hh; n split
};

// ---------------- tile staging ------------------------------------------------
// SW rows: [0..23] l0 hh | [24..47] l1 ih | [48..71] l1 hh ; row = blk*24+gate*8+c
template <bool DO_L1>
__device__ __forceinline__ void stage(
    int g, int buf, int ktg, int t8, int col0,
    const float* __restrict__ Whh0, const float* __restrict__ Wih1,
    const float* __restrict__ Whh1,
    const float* __restrict__ h0cur, const float* __restrict__ h1prev)
{
    float* sw  = SWp(g, buf);
    float* sh0 = SH0p(g, buf);
    const int NR8 = (DO_L1 ? 72 : 24) * 8;
    for (int i = t8; i < NR8; i += GSZ) {
        int r = i >> 3, f = i & 7;
        const float* src; int rr;
        if (!DO_L1 || r < 24)      { src = Whh0; rr = r; }
        else if (r < 48)           { src = Wih1; rr = r - 24; }
        else                       { src = Whh1; rr = r - 48; }
        int gate = rr >> 3, c = rr & 7;
        cpasync16(sw + r * STR + f * 4,
                  src + (size_t)(gate * D + col0 + c) * D + ktg + f * 4);
    }
#pragma unroll
    for (int i = t8; i < BATCH * 8; i += GSZ) {
        int b = i >> 3, f = i & 7;
        cpasync16(sh0 + b * STR + f * 4, h0cur + b * D + ktg + f * 4);
    }
    if (DO_L1) {
        float* sh1 = SH1p(g, buf);
#pragma unroll
        for (int i = t8; i < BATCH * 8; i += GSZ) {
            int b = i >> 3, f = i & 7;
            cpasync16(sh1 + b * STR + f * 4, h1prev + b * D + ktg + f * 4);
        }
    }
}

// ---------------- fused dual-layer mainloop ----------------------------------
template <bool DO_L1>
__device__ __forceinline__ void run_tiles(
    const float* __restrict__ Whh0, const float* __restrict__ Wih1,
    const float* __restrict__ Whh1,
    const float* __restrict__ h0cur, const float* __restrict__ h1prev,
    int col0, int tid, Acc& A)
{
    const int g  = tid >> 8;
    const int t8 = tid & 255;
    const int bg = t8 & 7;
    const int cl = (t8 >> 3) & 7;
    const int jh = t8 >> 6;
    const int b0 = bg + 8 * jh;

    A = Acc{};

    stage<DO_L1>(g, 0, g * 512, t8, col0, Whh0, Wih1, Whh1, h0cur, h1prev);
    CP_COMMIT();

    for (int tile = 0; tile < NT_G; tile++) {
        CP_WAIT0();
        __syncthreads();
        if (tile + 1 < NT_G) {
            stage<DO_L1>(g, (tile + 1) & 1, g * 512 + (tile + 1) * KT,
                         t8, col0, Whh0, Wih1, Whh1, h0cur, h1prev);
            CP_COMMIT();
        }
        const float* pw  = SWp(g, tile & 1) + cl * STR;
        const float* ph0 = SH0p(g, tile & 1) + b0 * STR;
        const float* ph1 = SH1p(g, tile & 1) + b0 * STR;
#pragma unroll
        for (int q = 0; q < KT / 4; q++) {
            const int o = 4 * q;
            ulonglong2 wAR = *(const ulonglong2*)(pw + o);
            ulonglong2 wAZ = *(const ulonglong2*)(pw + 8 * STR + o);
            ulonglong2 wAN = *(const ulonglong2*)(pw + 16 * STR + o);
            ulonglong2 h0a = *(const ulonglong2*)(ph0 + o);
            ulonglong2 h0b = *(const ulonglong2*)(ph0 + 32 * STR + o);
            ffma2(A.aR0, wAR.x, h0a.x); ffma2(A.aR0, wAR.y, h0a.y);
            ffma2(A.aZ0, wAZ.x, h0a.x); ffma2(A.aZ0, wAZ.y, h0a.y);
            ffma2(A.aH0, wAN.x, h0a.x); ffma2(A.aH0, wAN.y, h0a.y);
            ffma2(A.aR1, wAR.x, h0b.x); ffma2(A.aR1, wAR.y, h0b.y);
            ffma2(A.aZ1, wAZ.x, h0b.x); ffma2(A.aZ1, wAZ.y, h0b.y);
            ffma2(A.aH1, wAN.x, h0b.x); ffma2(A.aH1, wAN.y, h0b.y);
            if (DO_L1) {
                ulonglong2 wBR = *(const ulonglong2*)(pw + 24 * STR + o);
                ulonglong2 wBZ = *(const ulonglong2*)(pw + 32 * STR + o);
                ulonglong2 wBN = *(const ulonglong2*)(pw + 40 * STR + o);
                ulonglong2 wCR = *(const ulonglong2*)(pw + 48 * STR + o);
                ulonglong2 wCZ = *(const ulonglong2*)(pw + 56 * STR + o);
                ulonglong2 wCN = *(const ulonglong2*)(pw + 64 * STR + o);
                ulonglong2 h1a = *(const ulonglong2*)(ph1 + o);
                ulonglong2 h1b = *(const ulonglong2*)(ph1 + 32 * STR + o);
                ffma2(A.R0, wBR.x, h0a.x);  ffma2(A.R0, wBR.y, h0a.y);
                ffma2(A.R0, wCR.x, h1a.x);  ffma2(A.R0, wCR.y, h1a.y);
                ffma2(A.Z0, wBZ.x, h0a.x);  ffma2(A.Z0, wBZ.y, h0a.y);
                ffma2(A.Z0, wCZ.x, h1a.x);  ffma2(A.Z0, wCZ.y, h1a.y);
                ffma2(A.IN0, wBN.x, h0a.x); ffma2(A.IN0, wBN.y, h0a.y);
                ffma2(A.HN0, wCN.x, h1a.x); ffma2(A.HN0, wCN.y, h1a.y);
                ffma2(A.R1, wBR.x, h0b.x);  ffma2(A.R1, wBR.y, h0b.y);
                ffma2(A.R1, wCR.x, h1b.x);  ffma2(A.R1, wCR.y, h1b.y);
                ffma2(A.Z1, wBZ.x, h0b.x);  ffma2(A.Z1, wBZ.y, h0b.y);
                ffma2(A.Z1, wCZ.x, h1b.x);  ffma2(A.Z1, wCZ.y, h1b.y);
                ffma2(A.IN1, wBN.x, h0b.x); ffma2(A.IN1, wBN.y, h0b.y);
                ffma2(A.HN1, wCN.x, h1b.x); ffma2(A.HN1, wCN.y, h1b.y);
            }
        }
    }

    // group 1 publishes its K-half partials
    if (g == 1) {
#pragma unroll
        for (int i = 0; i < 2; i++) {
            int b = b0 + 32 * i;
            float* dst = SPART + (cl * 64 + b) * 8;
            *(float4*)dst = make_float4(hadd2(i ? A.aR1 : A.aR0),
                                        hadd2(i ? A.aZ1 : A.aZ0),
                                        hadd2(i ? A.aH1 : A.aH0),
                                        hadd2(i ? A.R1 : A.R0));
            *(float4*)(dst + 4) = make_float4(hadd2(i ? A.Z1 : A.Z0),
                                              hadd2(i ? A.IN1 : A.IN0),
                                              hadd2(i ? A.HN1 : A.HN0), 0.0f);
        }
    }
    __syncthreads();
}

// ---------------- epilogues (group 0 threads only) ---------------------------
__device__ __forceinline__ void epi_l1(
    const Acc& A, const float* __restrict__ bih1, const float* __restrict__ bhh1,
    float hp1a, float hp1b, float* __restrict__ h1out, int col, int cl, int b0)
{
    float br  = __ldg(bih1 + col)         + __ldg(bhh1 + col);
    float bz  = __ldg(bih1 + D + col)     + __ldg(bhh1 + D + col);
    float bni = __ldg(bih1 + 2 * D + col);
    float bnh = __ldg(bhh1 + 2 * D + col);
#pragma unroll
    for (int i = 0; i < 2; i++) {
        int b = b0 + 32 * i;
        const float* P = SPART + (cl * 64 + b) * 8;
        float r   = hadd2(i ? A.R1 : A.R0)   + P[3] + br;
        float z   = hadd2(i ? A.Z1 : A.Z0)   + P[4] + bz;
        float in_ = hadd2(i ? A.IN1 : A.IN0) + P[5] + bni;
        float hn  = hadd2(i ? A.HN1 : A.HN0) + P[6] + bnh;
        r = sigmoidf_(r); z = sigmoidf_(z);
        float n = tanhf(in_ + r * hn);
        h1out[b * D + col] = (1.0f - z) * n + z * (i ? hp1b : hp1a);
    }
}

__device__ __forceinline__ void epi_l0(
    const Acc& A, const float* __restrict__ bih0, const float* __restrict__ bhh0,
    const float* __restrict__ wsm, bool teach,
    float hp0a, float hp0b, float* __restrict__ h0out, int col, int cl, int b0)
{
    float br  = __ldg(bih0 + col)         + __ldg(bhh0 + col);
    float bz  = __ldg(bih0 + D + col)     + __ldg(bhh0 + D + col);
    float bni = __ldg(bih0 + 2 * D + col);
    float bnh = __ldg(bhh0 + 2 * D + col);
#pragma unroll
    for (int i = 0; i < 2; i++) {
        int b = b0 + 32 * i;
        const float* P = SPART + (cl * 64 + b) * 8;
        float r   = hadd2(i ? A.aR1 : A.aR0) + P[0] + br;
        float z   = hadd2(i ? A.aZ1 : A.aZ0) + P[1] + bz;
        float hn  = hadd2(i ? A.aH1 : A.aH0) + P[2] + bnh;
        float in_ = bni;
#pragma unroll
        for (int k = 0; k < 11; k++) {
            float xv;
            if (k < 7) xv = teach ? SXS[b * 12 + k] : __ldcg(g_pred + b * 8 + k);
            else       xv = SXS[b * 12 + k];
            r   += wsm[cl * 11 + k]       * xv;
            z   += wsm[88 + cl * 11 + k]  * xv;
            in_ += wsm[176 + cl * 11 + k] * xv;
        }
        r = sigmoidf_(r); z = sigmoidf_(z);
        float n = tanhf(in_ + r * hn);
        h0out[b * D + col] = (1.0f - z) * n + z * (i ? hp0b : hp0a);
    }
}

// ---------------- init -------------------------------------------------------
__global__ void gru_init_kernel() {
    int i = blockIdx.x * blockDim.x + threadIdx.x;
    if (i < BATCH * D) { g_h0[0][i] = 0.0f; g_h1[0][i] = 0.0f; }
    if (i < BATCH * 8) g_pred[i] = 0.0f;
    if (i == 0) { g_arrive = 0u; g_release = 0u; }
}

// ---------------- main persistent kernel ------------------------------------
__global__ void __launch_bounds__(NTHR, 1) gru_persistent_kernel(
    const float* __restrict__ xe,  const float* __restrict__ xme,
    const float* __restrict__ xd,  const float* __restrict__ xmd,
    const float* __restrict__ eWih0, const float* __restrict__ eWhh0,
    const float* __restrict__ ebih0, const float* __restrict__ ebhh0,
    const float* __restrict__ eWih1, const float* __restrict__ eWhh1,
    const float* __restrict__ ebih1, const float* __restrict__ ebhh1,
    const float* __restrict__ dWih0, const float* __restrict__ dWhh0,
    const float* __restrict__ dbih0, const float* __restrict__ dbhh0,
    const float* __restrict__ dWih1, const float* __restrict__ dWhh1,
    const float* __restrict__ dbih1, const float* __restrict__ dbhh1,
    const float* __restrict__ outW,  const float* __restrict__ outb,
    float* __restrict__ out)
{
    const int tid  = threadIdx.x;
    const int col0 = blockIdx.x * 8;
    const int g  = tid >> 8;
    const int t8 = tid & 255;
    const int cl = (t8 >> 3) & 7;
    const int b0 = (t8 & 7) + 8 * (t8 >> 6);
    const int col = col0 + cl;
    unsigned barNo = 0;
    int ph0 = 0, q1 = 0;   // buffers holding h0(t-ish prev) and h1(t-1)

    // preload small-x weights (l0 enc + l0 dec) into smem once
    for (int i = tid; i < 264; i += NTHR) {
        int gg = i / 88, r2 = i - gg * 88;
        int c = r2 / 11, k = r2 - c * 11;
        SWSM[i]       = __ldg(eWih0 + (size_t)(gg * D + col0 + c) * 11 + k);
        SWSM[264 + i] = __ldg(dWih0 + (size_t)(gg * D + col0 + c) * 11 + k);
    }
    __syncthreads();

    // ---- standalone enc l0(0) ----
    {
        for (int i = tid; i < BATCH * 11; i += NTHR) {
            int b = i / 11, k = i - b * 11;
            SXS[b * 12 + k] = (k < 7) ? __ldg(xe + (size_t)(b * SEQL + 0) * 7 + k)
                                      : __ldg(xme + (size_t)(b * SEQL + 0) * 4 + (k - 7));
        }
        Acc A;
        run_tiles<false>(eWhh0, nullptr, nullptr, g_h0[ph0], nullptr, col0, tid, A);
        if (g == 0)
            epi_l0(A, ebih0, ebhh0, SWSM, true, 0.0f, 0.0f, g_h0[ph0 ^ 1], col, cl, b0);
        barNo++; grid_sync(barNo);
        ph0 ^= 1;   // h0(0)
    }

    // ---- encoder fused phases: t = 0..191 computes l1(t) + l0(t+1) ----
    for (int t = 0; t < SEQL; t++) {
        int tt = (t + 1 < SEQL) ? t + 1 : SEQL - 1;
        for (int i = tid; i < BATCH * 11; i += NTHR) {
            int b = i / 11, k = i - b * 11;
            SXS[b * 12 + k] = (k < 7) ? __ldg(xe + (size_t)(b * SEQL + tt) * 7 + k)
                                      : __ldg(xme + (size_t)(b * SEQL + tt) * 4 + (k - 7));
        }
        const float* h0c = g_h0[ph0];
        const float* h1p = g_h1[q1];
        float hp0a = 0, hp0b = 0, hp1a = 0, hp1b = 0;
        if (g == 0) {
            hp0a = __ldcg(h0c + b0 * D + col);  hp0b = __ldcg(h0c + (b0 + 32) * D + col);
            hp1a = __ldcg(h1p + b0 * D + col);  hp1b = __ldcg(h1p + (b0 + 32) * D + col);
        }
        Acc A;
        run_tiles<true>(eWhh0, eWih1, eWhh1, h0c, h1p, col0, tid, A);
        if (g == 0) {
            epi_l1(A, ebih1, ebhh1, hp1a, hp1b, g_h1[q1 ^ 1], col, cl, b0);
            epi_l0(A, ebih0, ebhh0, SWSM, true, hp0a, hp0b, g_h0[ph0 ^ 1], col, cl, b0);
        }
        barNo++; grid_sync(barNo);
        ph0 ^= 1; q1 ^= 1;
    }
    ph0 ^= 1;  // last enc phase's h0 output is garbage; point back to h0(191)

    // ---- standalone dec l0(0) ----
    {
        for (int i = tid; i < BATCH * 11; i += NTHR) {
            int b = i / 11, k = i - b * 11;
            SXS[b * 12 + k] = (k < 7) ? __ldg(xd + (size_t)(b * DECLEN + 0) * 7 + k)
                                      : __ldg(xmd + (size_t)(b * DECLEN + 0) * 4 + (k - 7));
        }
        const float* h0c = g_h0[ph0];
        float hp0a = 0, hp0b = 0;
        if (g == 0) {
            hp0a = __ldcg(h0c + b0 * D + col);  hp0b = __ldcg(h0c + (b0 + 32) * D + col);
        }
        Acc A;
        run_tiles<false>(dWhh0, nullptr, nullptr, h0c, nullptr, col0, tid, A);
        if (g == 0)
            epi_l0(A, dbih0, dbhh0, SWSM + 264, true, hp0a, hp0b, g_h0[ph0 ^ 1], col, cl, b0);
        barNo++; grid_sync(barNo);
        ph0 ^= 1;   // h0_dec(0)
    }

    // ---- decoder fused phases: t = 0..215 computes l1(t) + l0(t+1) ----
    for (int t = 0; t < DECLEN; t++) {
        int tt = (t + 1 < DECLEN) ? t + 1 : DECLEN - 1;
        bool teach = (t + 1 < LABELN);
        for (int i = tid; i < BATCH * 11; i += NTHR) {
            int b = i / 11, k = i - b * 11;
            float v;
            if (k >= 7)     v = __ldg(xmd + (size_t)(b * DECLEN + tt) * 4 + (k - 7));
            else if (teach) v = __ldg(xd + (size_t)(b * DECLEN + tt) * 7 + k);
            else            v = 0.0f;  // x comes from g_pred in the epilogue
            SXS[b * 12 + k] = v;
        }
        const float* h0c = g_h0[ph0];
        const float* h1p = g_h1[q1];
        float hp0a = 0, hp0b = 0, hp1a = 0, hp1b = 0;
        if (g == 0) {
            hp0a = __ldcg(h0c + b0 * D + col);  hp0b = __ldcg(h0c + (b0 + 32) * D + col);
            hp1a = __ldcg(h1p + b0 * D + col);  hp1b = __ldcg(h1p + (b0 + 32) * D + col);
        }
        Acc A;
        run_tiles<true>(dWhh0, dWih1, dWhh1, h0c, h1p, col0, tid, A);
        if (g == 0)
            epi_l1(A, dbih1, dbhh1, hp1a, hp1b, g_h1[q1 ^ 1], col, cl, b0);

        if (t >= LABELN - 1) {     // pred(t) needed (feedback at t=47, output at t>=48)
            barNo++; grid_sync(barNo);
            if (blockIdx.x < BATCH) {
                int b = blockIdx.x;
                const float* h1c = g_h1[q1 ^ 1];
                float acc[7] = {0, 0, 0, 0, 0, 0, 0};
#pragma unroll
                for (int kb = 0; kb < 2; kb++) {
                    int k = kb * NTHR + tid;
                    float hv = __ldcg(h1c + b * D + k);
#pragma unroll
                    for (int j = 0; j < 7; j++)
                        acc[j] += __ldg(outW + j * D + k) * hv;
                }
#pragma unroll
                for (int j = 0; j < 7; j++)
                    for (int off = 16; off; off >>= 1)
                        acc[j] += __shfl_down_sync(0xffffffffu, acc[j], off);
                int lane = tid & 31, w = tid >> 5;
                if (lane == 0) {
#pragma unroll
                    for (int j = 0; j < 7; j++) SRED[w * 7 + j] = acc[j];
                }
                __syncthreads();
                if (tid < 7) {
                    float s = __ldg(outb + tid);
#pragma unroll
                    for (int w2 = 0; w2 < 16; w2++) s += SRED[w2 * 7 + tid];
                    g_pred[b * 8 + tid] = s;
                    if (t >= LABELN)
                        out[(size_t)b * (PREDN * 7) + (t - LABELN) * 7 + tid] = s;
                }
            }
            barNo++; grid_sync(barNo);
        }

        if (t < DECLEN - 1 && g == 0)
            epi_l0(A, dbih0, dbhh0, SWSM + 264, teach, hp0a, hp0b,
                   g_h0[ph0 ^ 1], col, cl, b0);
        barNo++; grid_sync(barNo);
        ph0 ^= 1; q1 ^= 1;
    }
}

// ---------------- launch -----------------------------------------------------
extern "C" void kernel_launch(void* const* d_in, const int* in_sizes, int n_in,
                              void* d_out, int out_size) {
    (void)in_sizes; (void)n_in; (void)out_size;
    const float* xe    = (const float*)d_in[0];
    const float* xme   = (const float*)d_in[1];
    const float* xd    = (const float*)d_in[2];
    const float* xmd   = (const float*)d_in[3];
    const float* eWih0 = (const float*)d_in[4];
    const float* eWhh0 = (const float*)d_in[5];
    const float* ebih0 = (const float*)d_in[6];
    const float* ebhh0 = (const float*)d_in[7];
    const float* eWih1 = (const float*)d_in[8];
    const float* eWhh1 = (const float*)d_in[9];
    const float* ebih1 = (const float*)d_in[10];
    const float* ebhh1 = (const float*)d_in[11];
    const float* dWih0 = (const float*)d_in[12];
    const float* dWhh0 = (const float*)d_in[13];
    const float* dbih0 = (const float*)d_in[14];
    const float* dbhh0 = (const float*)d_in[15];
    const float* dWih1 = (const float*)d_in[16];
    const float* dWhh1 = (const float*)d_in[17];
    const float* dbih1 = (const float*)d_in[18];
    const float* dbhh1 = (const float*)d_in[19];
    const float* outW  = (const float*)d_in[20];
    const float* outb  = (const float*)d_in[21];

    static int attr_set = 0;
    if (!attr_set) {
        cudaFuncSetAttribute(gru_persistent_kernel,
                             cudaFuncAttributeMaxDynamicSharedMemorySize,
                             SMEM_FLOATS * (int)sizeof(float));
        attr_set = 1;
    }

    gru_init_kernel<<<(BATCH * D + 255) / 256, 256>>>();
    gru_persistent_kernel<<<NCTA, NTHR, SMEM_FLOATS * sizeof(float)>>>(
        xe, xme, xd, xmd,
        eWih0, eWhh0, ebih0, ebhh0, eWih1, eWhh1, ebih1, ebhh1,
        dWih0, dWhh0, dbih0, dbhh0, dWih1, dWhh1, dbih1, dbhh1,
        outW, outb, (float*)d_out);
}